// round 16
// baseline (speedup 1.0000x reference)
#include <cuda_runtime.h>
#include <cuda_fp16.h>
#include <math.h>

#define NNODES 100000
#define DIN 256
#define DOUT 64
#define NEDGE 3200000
#define SCAN_BLK 1024
#define NB ((NNODES + SCAN_BLK - 1) / SCAN_BLK)   // 98

// ---------------- scratch (device globals; no allocation allowed) ----------------
__device__ float   g_self_p[NNODES * DOUT];    // x_p @ w_self_p   (fp32)
__device__ float   g_self_a[NNODES * DOUT];    // x_a @ w_self_a
__device__ __half2 g_rels_p[NNODES * DOUT/2];  // x_p @ w_rel_a_p  (fp16 gather table)
__device__ __half2 g_rels_a[NNODES * DOUT/2];  // x_a @ w_rel_p_a
__device__ float   g_vkq[4 * DOUT];

// CSR build scratch (2 relations)
__device__ int  g_cnt[2][NNODES];
__device__ int  g_off[2][NNODES];
__device__ int  g_cur[2][NNODES];
__device__ int  g_bsum[2][NB + 1];
__device__ int2 g_edge[2][NEDGE];              // packed {col, val-bits}

// ---------------- fold attention projections into 64-vectors ----------------
__global__ void vkq_kernel(const float* __restrict__ wk_p, const float* __restrict__ wq_p,
                           const float* __restrict__ wa_p,
                           const float* __restrict__ wk_a, const float* __restrict__ wq_a,
                           const float* __restrict__ wa_a) {
    int t = threadIdx.x;
    if (t >= 4 * DOUT) return;
    int which = t >> 6, d = t & 63;
    const float* W; const float* a;
    if (which == 0)      { W = wk_p; a = wa_p; }
    else if (which == 1) { W = wq_p; a = wa_p + DOUT; }
    else if (which == 2) { W = wk_a; a = wa_a; }
    else                 { W = wq_a; a = wa_a + DOUT; }
    float s = 0.f;
#pragma unroll 16
    for (int i = 0; i < DOUT; i++) s += W[d * DOUT + i] * a[i];
    g_vkq[which * DOUT + d] = s;
}

// ---------------- CSR build (single relation per launch) ----------------
__global__ void zero_cnt_kernel(int* __restrict__ cnt) {
    int i = blockIdx.x * blockDim.x + threadIdx.x;
    if (i < NNODES) cnt[i] = 0;
}

__global__ void hist_kernel(const int* __restrict__ row, int* __restrict__ cnt) {
    int e = blockIdx.x * blockDim.x + threadIdx.x;
    if (e < NEDGE) atomicAdd(cnt + __ldg(row + e), 1);
}

__global__ void scan1_kernel(const int* __restrict__ cnt, int* __restrict__ off,
                             int* __restrict__ bsum) {
    __shared__ int s[SCAN_BLK];
    int t = threadIdx.x;
    int i = blockIdx.x * SCAN_BLK + t;
    int v = (i < NNODES) ? cnt[i] : 0;
    s[t] = v;
    __syncthreads();
#pragma unroll
    for (int o = 1; o < SCAN_BLK; o <<= 1) {
        int x = (t >= o) ? s[t - o] : 0;
        __syncthreads();
        s[t] += x;
        __syncthreads();
    }
    if (i < NNODES) off[i] = s[t] - v;      // exclusive within block
    if (t == SCAN_BLK - 1) bsum[blockIdx.x] = s[t];
}

__global__ void scan2_kernel(int* __restrict__ bsum) {
    __shared__ int s[128];
    int t = threadIdx.x;
    int v = (t < NB) ? bsum[t] : 0;
    s[t] = v;
    __syncthreads();
#pragma unroll
    for (int o = 1; o < 128; o <<= 1) {
        int x = (t < 128 && t >= o) ? s[t - o] : 0;
        __syncthreads();
        s[t] += x;
        __syncthreads();
    }
    if (t < NB) bsum[t] = s[t] - v;          // exclusive
}

__global__ void scan3_kernel(int* __restrict__ off, int* __restrict__ cur,
                             const int* __restrict__ bsum) {
    int i = blockIdx.x * blockDim.x + threadIdx.x;
    if (i < NNODES) {
        int o = off[i] + bsum[i >> 10];
        off[i] = o;
        cur[i] = o;
    }
}

__global__ void scatter_kernel(const int* __restrict__ row, const int* __restrict__ col,
                               const float* __restrict__ val, int* __restrict__ cur,
                               int2* __restrict__ edges) {
    int e = blockIdx.x * blockDim.x + threadIdx.x;
    if (e >= NEDGE) return;
    int r = __ldg(row + e);
    int pos = atomicAdd(cur + r, 1);
    edges[pos] = make_int2(__ldg(col + e), __float_as_int(__ldg(val + e)));
}

// ------- fused SpMM + attention + output: warp per dst node, one relation ----------
// R13/R15 body verbatim; min-blocks=3 guarantees >=24 warps/SM (cap at 85 regs sits
// above the ~75-80 live set, unlike R9's 64-reg spill disaster).
__global__ __launch_bounds__(256, 3) void spmm_final_kernel(
    const int* __restrict__ off, const int* __restrict__ cnt, const int2* __restrict__ edges,
    const __half2* __restrict__ src, const float* __restrict__ selfft,
    const float* __restrict__ bias, const float* __restrict__ vk,
    const float* __restrict__ vq, float* __restrict__ out, float* __restrict__ att)
{
    int gw = (blockIdx.x * blockDim.x + threadIdx.x) >> 5;
    int lane = threadIdx.x & 31;
    if (gw >= NNODES) return;

    int start = __ldg(off + gw);
    int deg   = __ldg(cnt + gw);

    float a0 = 0.f, a1 = 0.f, b0 = 0.f, b1 = 0.f;
    int i = 0;
    for (; i + 8 <= deg; i += 8) {
        int2 e[8];
#pragma unroll
        for (int u = 0; u < 8; u++) e[u] = __ldg(edges + start + i + u);
        __half2 h[8];
#pragma unroll
        for (int u = 0; u < 8; u++) h[u] = __ldg(src + (size_t)e[u].x * 32 + lane);
#pragma unroll
        for (int u = 0; u < 8; u++) {
            float2 f = __half22float2(h[u]);
            float v = __int_as_float(e[u].y);
            if (u & 1) { b0 = fmaf(v, f.x, b0); b1 = fmaf(v, f.y, b1); }
            else       { a0 = fmaf(v, f.x, a0); a1 = fmaf(v, f.y, a1); }
        }
    }
    if (i + 4 <= deg) {
        int2 e[4];
#pragma unroll
        for (int u = 0; u < 4; u++) e[u] = __ldg(edges + start + i + u);
        __half2 h[4];
#pragma unroll
        for (int u = 0; u < 4; u++) h[u] = __ldg(src + (size_t)e[u].x * 32 + lane);
#pragma unroll
        for (int u = 0; u < 4; u++) {
            float2 f = __half22float2(h[u]);
            float v = __int_as_float(e[u].y);
            if (u & 1) { b0 = fmaf(v, f.x, b0); b1 = fmaf(v, f.y, b1); }
            else       { a0 = fmaf(v, f.x, a0); a1 = fmaf(v, f.y, a1); }
        }
        i += 4;
    }
    for (; i < deg; i++) {
        int2 e0 = __ldg(edges + start + i);
        __half2 h0 = __ldg(src + (size_t)e0.x * 32 + lane);
        float v0 = __int_as_float(e0.y);
        float2 f0 = __half22float2(h0);
        a0 = fmaf(v0, f0.x, a0); a1 = fmaf(v0, f0.y, a1);
    }
    float n0 = a0 + b0, n1 = a1 + b1;

    // ---- attention epilogue ----
    size_t base = (size_t)gw * DOUT;
    float2 s = *(const float2*)(selfft + base + 2 * lane);
    float2 k = *(const float2*)(vk + 2 * lane);
    float2 q = *(const float2*)(vq + 2 * lane);
    float2 b = *(const float2*)(bias + 2 * lane);

    float d_skq = s.x * (k.x + q.x) + s.y * (k.y + q.y);
    float d_sq  = s.x * q.x + s.y * q.y;
    float d_nk  = n0 * k.x + n1 * k.y;
#pragma unroll
    for (int o = 16; o; o >>= 1) {
        d_skq += __shfl_xor_sync(0xffffffffu, d_skq, o);
        d_sq  += __shfl_xor_sync(0xffffffffu, d_sq,  o);
        d_nk  += __shfl_xor_sync(0xffffffffu, d_nk,  o);
    }
    float e0v = d_skq;
    float e1v = d_nk + d_sq;
    e0v = (e0v > 0.f) ? e0v : expm1f(e0v);   // elu
    e1v = (e1v > 0.f) ? e1v : expm1f(e1v);
    float m = fmaxf(e0v, e1v);
    float w0 = expf(e0v - m), w1 = expf(e1v - m);
    float inv = 1.f / (w0 + w1);
    w0 *= inv; w1 *= inv;

    float2 o2 = make_float2(fmaf(w0, s.x, fmaf(w1, n0, b.x)),
                            fmaf(w0, s.y, fmaf(w1, n1, b.y)));
    *(float2*)(out + base + 2 * lane) = o2;
    if (lane == 0) { att[(size_t)gw * 2] = w0; att[(size_t)gw * 2 + 1] = w1; }
}

// ---------------- tf32 tensor-core dual GEMM, 3-stage cp.async pipeline ----------------
#define GBM 128
#define GBK 32
#define NT (DIN / GBK)                 // 8 k-tiles
#define A_STRIDE 36
#define B_STRIDE 136
#define A_STAGE (GBM * A_STRIDE)
#define B_STAGE (GBK * B_STRIDE)
#define GEMM_SMEM_BYTES (3 * (A_STAGE + B_STAGE) * 4)   // 107520 B

__device__ __forceinline__ unsigned f2tf32(float f) {
    unsigned u;
    asm("cvt.rna.tf32.f32 %0, %1;" : "=r"(u) : "f"(f));
    return u;
}

__device__ __forceinline__ void cp16(float* dst, const float* src) {
    unsigned d = (unsigned)__cvta_generic_to_shared(dst);
    asm volatile("cp.async.ca.shared.global [%0], [%1], 16;\n" :: "r"(d), "l"(src));
}

__global__ __launch_bounds__(256) void gemm_tf32_kernel(
    const float* __restrict__ X, const float* __restrict__ Ws, const float* __restrict__ Wr,
    float* __restrict__ Cs, __half* __restrict__ Cr, int nrows)
{
    extern __shared__ float sm[];
    float* Asm = sm;                         // [3][GBM][A_STRIDE]
    float* Bsm = sm + 3 * A_STAGE;           // [3][GBK][B_STRIDE]

    const int tid = threadIdx.x;
    const int wid = tid >> 5, lane = tid & 31;
    const int g = lane >> 2, t4 = lane & 3;
    const int wr = wid >> 2, wc = wid & 3;
    const int mwarp = wr * 64, nwarp = wc * 32;
    const int rowbase = blockIdx.x * GBM;

    auto loadtile = [&](int kt, int st) {
        const int k0 = kt * GBK;
        float* Ast = Asm + st * A_STAGE;
        float* Bst = Bsm + st * B_STAGE;
#pragma unroll
        for (int j = 0; j < 4; j++) {
            int ci = tid + 256 * j;
            int r = ci >> 3, q = ci & 7;
            int gr = min(rowbase + r, NNODES - 1);
            cp16(Ast + r * A_STRIDE + q * 4, X + (size_t)gr * DIN + k0 + q * 4);
        }
#pragma unroll
        for (int j = 0; j < 4; j++) {
            int ci = tid + 256 * j;
            int k = ci >> 5, q = ci & 31;
            const float* src = (q < 16) ? Ws + (size_t)(k0 + k) * DOUT + q * 4
                                        : Wr + (size_t)(k0 + k) * DOUT + (q - 16) * 4;
            cp16(Bst + k * B_STRIDE + q * 4, src);
        }
    };

    float c[4][4][4];
#pragma unroll
    for (int mi = 0; mi < 4; mi++)
#pragma unroll
        for (int nj = 0; nj < 4; nj++)
#pragma unroll
            for (int u = 0; u < 4; u++) c[mi][nj][u] = 0.f;

    loadtile(0, 0);
    asm volatile("cp.async.commit_group;\n");
    loadtile(1, 1);
    asm volatile("cp.async.commit_group;\n");

#pragma unroll
    for (int kt = 0; kt < NT; kt++) {
        const int st = kt % 3;
        if (kt + 2 < NT) {
            loadtile(kt + 2, (kt + 2) % 3);
            asm volatile("cp.async.commit_group;\n");
            asm volatile("cp.async.wait_group 2;\n");
        } else if (kt + 1 < NT) {
            asm volatile("cp.async.wait_group 1;\n");
        } else {
            asm volatile("cp.async.wait_group 0;\n");
        }
        __syncthreads();

        const float* Ast = Asm + st * A_STAGE;
        const float* Bst = Bsm + st * B_STAGE;
#pragma unroll
        for (int k8 = 0; k8 < 4; k8++) {
            const int kk = k8 * 8;
            unsigned af[4][4];
#pragma unroll
            for (int mi = 0; mi < 4; mi++) {
                int mrow = mwarp + mi * 16;
                af[mi][0] = f2tf32(Ast[(mrow + g) * A_STRIDE + kk + t4]);
                af[mi][1] = f2tf32(Ast[(mrow + g + 8) * A_STRIDE + kk + t4]);
                af[mi][2] = f2tf32(Ast[(mrow + g) * A_STRIDE + kk + t4 + 4]);
                af[mi][3] = f2tf32(Ast[(mrow + g + 8) * A_STRIDE + kk + t4 + 4]);
            }
            unsigned bf[4][2];
#pragma unroll
            for (int nj = 0; nj < 4; nj++) {
                int ncol = nwarp + nj * 8 + g;
                bf[nj][0] = f2tf32(Bst[(kk + t4) * B_STRIDE + ncol]);
                bf[nj][1] = f2tf32(Bst[(kk + t4 + 4) * B_STRIDE + ncol]);
            }
#pragma unroll
            for (int mi = 0; mi < 4; mi++)
#pragma unroll
                for (int nj = 0; nj < 4; nj++) {
                    asm volatile(
                        "mma.sync.aligned.m16n8k8.row.col.f32.tf32.tf32.f32 "
                        "{%0,%1,%2,%3}, {%4,%5,%6,%7}, {%8,%9}, {%0,%1,%2,%3};"
                        : "+f"(c[mi][nj][0]), "+f"(c[mi][nj][1]),
                          "+f"(c[mi][nj][2]), "+f"(c[mi][nj][3])
                        : "r"(af[mi][0]), "r"(af[mi][1]), "r"(af[mi][2]), "r"(af[mi][3]),
                          "r"(bf[nj][0]), "r"(bf[nj][1]));
                }
        }
        __syncthreads();
    }

#pragma unroll
    for (int mi = 0; mi < 4; mi++) {
        int row0 = rowbase + mwarp + mi * 16 + g;
        int row1 = row0 + 8;
#pragma unroll
        for (int nj = 0; nj < 4; nj++) {
            int n = nwarp + nj * 8 + 2 * t4;
            if (wc < 2) {
                if (row0 < nrows)
                    *(float2*)(Cs + (size_t)row0 * DOUT + n) =
                        make_float2(c[mi][nj][0], c[mi][nj][1]);
                if (row1 < nrows)
                    *(float2*)(Cs + (size_t)row1 * DOUT + n) =
                        make_float2(c[mi][nj][2], c[mi][nj][3]);
            } else {
                int nn = n - 64;
                if (row0 < nrows)
                    *(__half2*)(Cr + (size_t)row0 * DOUT + nn) =
                        __floats2half2_rn(c[mi][nj][0], c[mi][nj][1]);
                if (row1 < nrows)
                    *(__half2*)(Cr + (size_t)row1 * DOUT + nn) =
                        __floats2half2_rn(c[mi][nj][2], c[mi][nj][3]);
            }
        }
    }
}

// ---------------- launch ----------------
extern "C" void kernel_launch(void* const* d_in, const int* in_sizes, int n_in,
                              void* d_out, int out_size) {
    const float* x_p       = (const float*)d_in[0];
    const float* x_a       = (const float*)d_in[1];
    const int*   adj_a_row = (const int*)d_in[2];
    const int*   adj_a_col = (const int*)d_in[3];
    const float* adj_a_val = (const float*)d_in[4];
    const int*   adj_p_row = (const int*)d_in[5];
    const int*   adj_p_col = (const int*)d_in[6];
    const float* adj_p_val = (const float*)d_in[7];
    const float* w_self_p  = (const float*)d_in[8];
    const float* w_rel_p_a = (const float*)d_in[9];
    const float* bias_p    = (const float*)d_in[10];
    const float* w_query_p = (const float*)d_in[11];
    const float* w_keys_p  = (const float*)d_in[12];
    const float* w_att_p   = (const float*)d_in[13];
    const float* w_self_a  = (const float*)d_in[14];
    const float* w_rel_a_p = (const float*)d_in[15];
    const float* bias_a    = (const float*)d_in[16];
    const float* w_query_a = (const float*)d_in[17];
    const float* w_keys_a  = (const float*)d_in[18];
    const float* w_att_a   = (const float*)d_in[19];

    float* out = (float*)d_out;
    float* out_p = out;
    float* out_a = out + (size_t)NNODES * DOUT;
    float* att_p = out + (size_t)2 * NNODES * DOUT;
    float* att_a = att_p + (size_t)NNODES * 2;

    float *p_self_p, *p_self_a, *p_vkq;
    __half2 *p_rels_p, *p_rels_a;
    int *p_cnt, *p_off, *p_cur, *p_bsum;
    int2 *p_edge;
    cudaGetSymbolAddress((void**)&p_self_p, g_self_p);
    cudaGetSymbolAddress((void**)&p_self_a, g_self_a);
    cudaGetSymbolAddress((void**)&p_rels_p, g_rels_p);
    cudaGetSymbolAddress((void**)&p_rels_a, g_rels_a);
    cudaGetSymbolAddress((void**)&p_vkq, g_vkq);
    cudaGetSymbolAddress((void**)&p_cnt, g_cnt);
    cudaGetSymbolAddress((void**)&p_off, g_off);
    cudaGetSymbolAddress((void**)&p_cur, g_cur);
    cudaGetSymbolAddress((void**)&p_bsum, g_bsum);
    cudaGetSymbolAddress((void**)&p_edge, g_edge);

    static cudaStream_t s1 = nullptr, s2 = nullptr, s3 = nullptr;
    static cudaEvent_t e_fork = nullptr, e_b0 = nullptr,
                       e_ga = nullptr, e_gp = nullptr, e_s2 = nullptr, e_s3 = nullptr;
    if (s1 == nullptr) {
        cudaStreamCreateWithFlags(&s1, cudaStreamNonBlocking);
        cudaStreamCreateWithFlags(&s2, cudaStreamNonBlocking);
        cudaStreamCreateWithFlags(&s3, cudaStreamNonBlocking);
        cudaEventCreateWithFlags(&e_fork, cudaEventDisableTiming);
        cudaEventCreateWithFlags(&e_b0, cudaEventDisableTiming);
        cudaEventCreateWithFlags(&e_ga, cudaEventDisableTiming);
        cudaEventCreateWithFlags(&e_gp, cudaEventDisableTiming);
        cudaEventCreateWithFlags(&e_s2, cudaEventDisableTiming);
        cudaEventCreateWithFlags(&e_s3, cudaEventDisableTiming);
        cudaFuncSetAttribute(gemm_tf32_kernel,
                             cudaFuncAttributeMaxDynamicSharedMemorySize, GEMM_SMEM_BYTES);
    }

    const int EB = (NEDGE + 255) / 256;
    const int NBK = (NNODES + 255) / 256;
    const int gblocks = (NNODES + GBM - 1) / GBM;
    const int wblocks = (NNODES * 32 + 255) / 256;

    // fork: s1 builds rel0, s2 builds rel1 (concurrent), s0 runs GEMMs
    cudaEventRecord(e_fork, 0);
    cudaStreamWaitEvent(s1, e_fork, 0);
    cudaStreamWaitEvent(s2, e_fork, 0);

    // ---- s1: CSR build rel0 (adj_a) ----
    vkq_kernel<<<1, 256, 0, s1>>>(w_keys_p, w_query_p, w_att_p, w_keys_a, w_query_a, w_att_a);
    zero_cnt_kernel<<<NBK, 256, 0, s1>>>(p_cnt);
    hist_kernel<<<EB, 256, 0, s1>>>(adj_a_row, p_cnt);
    scan1_kernel<<<NB, SCAN_BLK, 0, s1>>>(p_cnt, p_off, p_bsum);
    scan2_kernel<<<1, 128, 0, s1>>>(p_bsum);
    scan3_kernel<<<NBK, 256, 0, s1>>>(p_off, p_cur, p_bsum);
    scatter_kernel<<<EB, 256, 0, s1>>>(adj_a_row, adj_a_col, adj_a_val, p_cur, p_edge);
    cudaEventRecord(e_b0, s1);

    // ---- s2: CSR build rel1 (adj_p) — concurrent with s1; spmm1 follows in-stream ----
    zero_cnt_kernel<<<NBK, 256, 0, s2>>>(p_cnt + NNODES);
    hist_kernel<<<EB, 256, 0, s2>>>(adj_p_row, p_cnt + NNODES);
    scan1_kernel<<<NB, SCAN_BLK, 0, s2>>>(p_cnt + NNODES, p_off + NNODES, p_bsum + (NB + 1));
    scan2_kernel<<<1, 128, 0, s2>>>(p_bsum + (NB + 1));
    scan3_kernel<<<NBK, 256, 0, s2>>>(p_off + NNODES, p_cur + NNODES, p_bsum + (NB + 1));
    scatter_kernel<<<EB, 256, 0, s2>>>(adj_p_row, adj_p_col, adj_p_val, p_cur + NNODES,
                                       p_edge + NEDGE);

    // ---- s0: pipelined tf32 GEMMs ----
    gemm_tf32_kernel<<<gblocks, 256, GEMM_SMEM_BYTES>>>(x_a, w_self_a, w_rel_p_a,
                                                        p_self_a, (__half*)p_rels_a, NNODES);
    cudaEventRecord(e_ga, 0);
    gemm_tf32_kernel<<<gblocks, 256, GEMM_SMEM_BYTES>>>(x_p, w_self_p, w_rel_a_p,
                                                        p_self_p, (__half*)p_rels_p, NNODES);
    cudaEventRecord(e_gp, 0);

    // ---- s3: spmm+finalize rel0 (out_p) — needs build0 + gemm_a ----
    cudaStreamWaitEvent(s3, e_b0, 0);
    cudaStreamWaitEvent(s3, e_ga, 0);
    spmm_final_kernel<<<wblocks, 256, 0, s3>>>(p_off, p_cnt, p_edge, p_rels_a, p_self_p, bias_p,
                                               p_vkq + 0 * DOUT, p_vkq + 1 * DOUT, out_p, att_p);
    cudaEventRecord(e_s3, s3);

    // ---- s2: spmm+finalize rel1 (out_a) — in-stream after build1; waits gemm_p ----
    cudaStreamWaitEvent(s2, e_gp, 0);
    spmm_final_kernel<<<wblocks, 256, 0, s2>>>(p_off + NNODES, p_cnt + NNODES, p_edge + NEDGE,
                                               p_rels_p, p_self_a, bias_a,
                                               p_vkq + 2 * DOUT, p_vkq + 3 * DOUT, out_a, att_a);
    cudaEventRecord(e_s2, s2);

    // join both SpMM streams back into the origin stream
    cudaStreamWaitEvent(0, e_s3, 0);
    cudaStreamWaitEvent(0, e_s2, 0);
}

// round 17
// speedup vs baseline: 1.2104x; 1.2104x over previous
#include <cuda_runtime.h>
#include <cuda_fp16.h>
#include <math.h>

#define NNODES 100000
#define DIN 256
#define DOUT 64
#define NEDGE 3200000
#define SCAN_BLK 1024
#define NB ((NNODES + SCAN_BLK - 1) / SCAN_BLK)   // 98

// ---------------- scratch (device globals; no allocation allowed) ----------------
__device__ float   g_self_p[NNODES * DOUT];    // x_p @ w_self_p   (fp32)
__device__ float   g_self_a[NNODES * DOUT];    // x_a @ w_self_a
__device__ __half2 g_rels_p[NNODES * DOUT/2];  // x_p @ w_rel_a_p  (fp16 gather table)
__device__ __half2 g_rels_a[NNODES * DOUT/2];  // x_a @ w_rel_p_a
__device__ float   g_vkq[4 * DOUT];

// CSR build scratch (2 relations)
__device__ int  g_cnt[2][NNODES];
__device__ int  g_off[2][NNODES];
__device__ int  g_cur[2][NNODES];
__device__ int  g_bsum[2][NB + 1];
__device__ int2 g_edge[2][NEDGE];              // packed {col, val-bits}

// ---------------- fold attention projections into 64-vectors ----------------
__global__ void vkq_kernel(const float* __restrict__ wk_p, const float* __restrict__ wq_p,
                           const float* __restrict__ wa_p,
                           const float* __restrict__ wk_a, const float* __restrict__ wq_a,
                           const float* __restrict__ wa_a) {
    int t = threadIdx.x;
    if (t >= 4 * DOUT) return;
    int which = t >> 6, d = t & 63;
    const float* W; const float* a;
    if (which == 0)      { W = wk_p; a = wa_p; }
    else if (which == 1) { W = wq_p; a = wa_p + DOUT; }
    else if (which == 2) { W = wk_a; a = wa_a; }
    else                 { W = wq_a; a = wa_a + DOUT; }
    float s = 0.f;
#pragma unroll 16
    for (int i = 0; i < DOUT; i++) s += W[d * DOUT + i] * a[i];
    g_vkq[which * DOUT + d] = s;
}

// ---------------- CSR build (single relation per launch) ----------------
__global__ void zero_cnt_kernel(int* __restrict__ cnt) {
    int i = blockIdx.x * blockDim.x + threadIdx.x;
    if (i < NNODES) cnt[i] = 0;
}

__global__ void hist_kernel(const int* __restrict__ row, int* __restrict__ cnt) {
    int e = blockIdx.x * blockDim.x + threadIdx.x;
    if (e < NEDGE) atomicAdd(cnt + __ldg(row + e), 1);
}

__global__ void scan1_kernel(const int* __restrict__ cnt, int* __restrict__ off,
                             int* __restrict__ bsum) {
    __shared__ int s[SCAN_BLK];
    int t = threadIdx.x;
    int i = blockIdx.x * SCAN_BLK + t;
    int v = (i < NNODES) ? cnt[i] : 0;
    s[t] = v;
    __syncthreads();
#pragma unroll
    for (int o = 1; o < SCAN_BLK; o <<= 1) {
        int x = (t >= o) ? s[t - o] : 0;
        __syncthreads();
        s[t] += x;
        __syncthreads();
    }
    if (i < NNODES) off[i] = s[t] - v;      // exclusive within block
    if (t == SCAN_BLK - 1) bsum[blockIdx.x] = s[t];
}

__global__ void scan2_kernel(int* __restrict__ bsum) {
    __shared__ int s[128];
    int t = threadIdx.x;
    int v = (t < NB) ? bsum[t] : 0;
    s[t] = v;
    __syncthreads();
#pragma unroll
    for (int o = 1; o < 128; o <<= 1) {
        int x = (t < 128 && t >= o) ? s[t - o] : 0;
        __syncthreads();
        s[t] += x;
        __syncthreads();
    }
    if (t < NB) bsum[t] = s[t] - v;          // exclusive
}

__global__ void scan3_kernel(int* __restrict__ off, int* __restrict__ cur,
                             const int* __restrict__ bsum) {
    int i = blockIdx.x * blockDim.x + threadIdx.x;
    if (i < NNODES) {
        int o = off[i] + bsum[i >> 10];
        off[i] = o;
        cur[i] = o;
    }
}

__global__ void scatter_kernel(const int* __restrict__ row, const int* __restrict__ col,
                               const float* __restrict__ val, int* __restrict__ cur,
                               int2* __restrict__ edges) {
    int e = blockIdx.x * blockDim.x + threadIdx.x;
    if (e >= NEDGE) return;
    int r = __ldg(row + e);
    int pos = atomicAdd(cur + r, 1);
    edges[pos] = make_int2(__ldg(col + e), __float_as_int(__ldg(val + e)));
}

// ------- fused SpMM + attention + output: warp per dst node, one relation ----------
// R15 body verbatim; 128-thread blocks: at ~96 regs/thread, 5 blocks/SM fit
// (20 warps) vs 2x256-thread blocks (16 warps). No register cap — no spills.
__global__ __launch_bounds__(128) void spmm_final_kernel(
    const int* __restrict__ off, const int* __restrict__ cnt, const int2* __restrict__ edges,
    const __half2* __restrict__ src, const float* __restrict__ selfft,
    const float* __restrict__ bias, const float* __restrict__ vk,
    const float* __restrict__ vq, float* __restrict__ out, float* __restrict__ att)
{
    int gw = (blockIdx.x * blockDim.x + threadIdx.x) >> 5;
    int lane = threadIdx.x & 31;
    if (gw >= NNODES) return;

    int start = __ldg(off + gw);
    int deg   = __ldg(cnt + gw);

    float a0 = 0.f, a1 = 0.f, b0 = 0.f, b1 = 0.f;
    int i = 0;
    for (; i + 8 <= deg; i += 8) {
        int2 e[8];
#pragma unroll
        for (int u = 0; u < 8; u++) e[u] = __ldg(edges + start + i + u);
        __half2 h[8];
#pragma unroll
        for (int u = 0; u < 8; u++) h[u] = __ldg(src + (size_t)e[u].x * 32 + lane);
#pragma unroll
        for (int u = 0; u < 8; u++) {
            float2 f = __half22float2(h[u]);
            float v = __int_as_float(e[u].y);
            if (u & 1) { b0 = fmaf(v, f.x, b0); b1 = fmaf(v, f.y, b1); }
            else       { a0 = fmaf(v, f.x, a0); a1 = fmaf(v, f.y, a1); }
        }
    }
    if (i + 4 <= deg) {
        int2 e[4];
#pragma unroll
        for (int u = 0; u < 4; u++) e[u] = __ldg(edges + start + i + u);
        __half2 h[4];
#pragma unroll
        for (int u = 0; u < 4; u++) h[u] = __ldg(src + (size_t)e[u].x * 32 + lane);
#pragma unroll
        for (int u = 0; u < 4; u++) {
            float2 f = __half22float2(h[u]);
            float v = __int_as_float(e[u].y);
            if (u & 1) { b0 = fmaf(v, f.x, b0); b1 = fmaf(v, f.y, b1); }
            else       { a0 = fmaf(v, f.x, a0); a1 = fmaf(v, f.y, a1); }
        }
        i += 4;
    }
    for (; i < deg; i++) {
        int2 e0 = __ldg(edges + start + i);
        __half2 h0 = __ldg(src + (size_t)e0.x * 32 + lane);
        float v0 = __int_as_float(e0.y);
        float2 f0 = __half22float2(h0);
        a0 = fmaf(v0, f0.x, a0); a1 = fmaf(v0, f0.y, a1);
    }
    float n0 = a0 + b0, n1 = a1 + b1;

    // ---- attention epilogue ----
    size_t base = (size_t)gw * DOUT;
    float2 s = *(const float2*)(selfft + base + 2 * lane);
    float2 k = *(const float2*)(vk + 2 * lane);
    float2 q = *(const float2*)(vq + 2 * lane);
    float2 b = *(const float2*)(bias + 2 * lane);

    float d_skq = s.x * (k.x + q.x) + s.y * (k.y + q.y);
    float d_sq  = s.x * q.x + s.y * q.y;
    float d_nk  = n0 * k.x + n1 * k.y;
#pragma unroll
    for (int o = 16; o; o >>= 1) {
        d_skq += __shfl_xor_sync(0xffffffffu, d_skq, o);
        d_sq  += __shfl_xor_sync(0xffffffffu, d_sq,  o);
        d_nk  += __shfl_xor_sync(0xffffffffu, d_nk,  o);
    }
    float e0v = d_skq;
    float e1v = d_nk + d_sq;
    e0v = (e0v > 0.f) ? e0v : expm1f(e0v);   // elu
    e1v = (e1v > 0.f) ? e1v : expm1f(e1v);
    float m = fmaxf(e0v, e1v);
    float w0 = expf(e0v - m), w1 = expf(e1v - m);
    float inv = 1.f / (w0 + w1);
    w0 *= inv; w1 *= inv;

    float2 o2 = make_float2(fmaf(w0, s.x, fmaf(w1, n0, b.x)),
                            fmaf(w0, s.y, fmaf(w1, n1, b.y)));
    *(float2*)(out + base + 2 * lane) = o2;
    if (lane == 0) { att[(size_t)gw * 2] = w0; att[(size_t)gw * 2 + 1] = w1; }
}

// ---------------- tf32 tensor-core dual GEMM, 3-stage cp.async pipeline ----------------
#define GBM 128
#define GBK 32
#define NT (DIN / GBK)                 // 8 k-tiles
#define A_STRIDE 36
#define B_STRIDE 136
#define A_STAGE (GBM * A_STRIDE)
#define B_STAGE (GBK * B_STRIDE)
#define GEMM_SMEM_BYTES (3 * (A_STAGE + B_STAGE) * 4)   // 107520 B

__device__ __forceinline__ unsigned f2tf32(float f) {
    unsigned u;
    asm("cvt.rna.tf32.f32 %0, %1;" : "=r"(u) : "f"(f));
    return u;
}

__device__ __forceinline__ void cp16(float* dst, const float* src) {
    unsigned d = (unsigned)__cvta_generic_to_shared(dst);
    asm volatile("cp.async.ca.shared.global [%0], [%1], 16;\n" :: "r"(d), "l"(src));
}

__global__ __launch_bounds__(256) void gemm_tf32_kernel(
    const float* __restrict__ X, const float* __restrict__ Ws, const float* __restrict__ Wr,
    float* __restrict__ Cs, __half* __restrict__ Cr, int nrows)
{
    extern __shared__ float sm[];
    float* Asm = sm;                         // [3][GBM][A_STRIDE]
    float* Bsm = sm + 3 * A_STAGE;           // [3][GBK][B_STRIDE]

    const int tid = threadIdx.x;
    const int wid = tid >> 5, lane = tid & 31;
    const int g = lane >> 2, t4 = lane & 3;
    const int wr = wid >> 2, wc = wid & 3;
    const int mwarp = wr * 64, nwarp = wc * 32;
    const int rowbase = blockIdx.x * GBM;

    auto loadtile = [&](int kt, int st) {
        const int k0 = kt * GBK;
        float* Ast = Asm + st * A_STAGE;
        float* Bst = Bsm + st * B_STAGE;
#pragma unroll
        for (int j = 0; j < 4; j++) {
            int ci = tid + 256 * j;
            int r = ci >> 3, q = ci & 7;
            int gr = min(rowbase + r, NNODES - 1);
            cp16(Ast + r * A_STRIDE + q * 4, X + (size_t)gr * DIN + k0 + q * 4);
        }
#pragma unroll
        for (int j = 0; j < 4; j++) {
            int ci = tid + 256 * j;
            int k = ci >> 5, q = ci & 31;
            const float* src = (q < 16) ? Ws + (size_t)(k0 + k) * DOUT + q * 4
                                        : Wr + (size_t)(k0 + k) * DOUT + (q - 16) * 4;
            cp16(Bst + k * B_STRIDE + q * 4, src);
        }
    };

    float c[4][4][4];
#pragma unroll
    for (int mi = 0; mi < 4; mi++)
#pragma unroll
        for (int nj = 0; nj < 4; nj++)
#pragma unroll
            for (int u = 0; u < 4; u++) c[mi][nj][u] = 0.f;

    loadtile(0, 0);
    asm volatile("cp.async.commit_group;\n");
    loadtile(1, 1);
    asm volatile("cp.async.commit_group;\n");

#pragma unroll
    for (int kt = 0; kt < NT; kt++) {
        const int st = kt % 3;
        if (kt + 2 < NT) {
            loadtile(kt + 2, (kt + 2) % 3);
            asm volatile("cp.async.commit_group;\n");
            asm volatile("cp.async.wait_group 2;\n");
        } else if (kt + 1 < NT) {
            asm volatile("cp.async.wait_group 1;\n");
        } else {
            asm volatile("cp.async.wait_group 0;\n");
        }
        __syncthreads();

        const float* Ast = Asm + st * A_STAGE;
        const float* Bst = Bsm + st * B_STAGE;
#pragma unroll
        for (int k8 = 0; k8 < 4; k8++) {
            const int kk = k8 * 8;
            unsigned af[4][4];
#pragma unroll
            for (int mi = 0; mi < 4; mi++) {
                int mrow = mwarp + mi * 16;
                af[mi][0] = f2tf32(Ast[(mrow + g) * A_STRIDE + kk + t4]);
                af[mi][1] = f2tf32(Ast[(mrow + g + 8) * A_STRIDE + kk + t4]);
                af[mi][2] = f2tf32(Ast[(mrow + g) * A_STRIDE + kk + t4 + 4]);
                af[mi][3] = f2tf32(Ast[(mrow + g + 8) * A_STRIDE + kk + t4 + 4]);
            }
            unsigned bf[4][2];
#pragma unroll
            for (int nj = 0; nj < 4; nj++) {
                int ncol = nwarp + nj * 8 + g;
                bf[nj][0] = f2tf32(Bst[(kk + t4) * B_STRIDE + ncol]);
                bf[nj][1] = f2tf32(Bst[(kk + t4 + 4) * B_STRIDE + ncol]);
            }
#pragma unroll
            for (int mi = 0; mi < 4; mi++)
#pragma unroll
                for (int nj = 0; nj < 4; nj++) {
                    asm volatile(
                        "mma.sync.aligned.m16n8k8.row.col.f32.tf32.tf32.f32 "
                        "{%0,%1,%2,%3}, {%4,%5,%6,%7}, {%8,%9}, {%0,%1,%2,%3};"
                        : "+f"(c[mi][nj][0]), "+f"(c[mi][nj][1]),
                          "+f"(c[mi][nj][2]), "+f"(c[mi][nj][3])
                        : "r"(af[mi][0]), "r"(af[mi][1]), "r"(af[mi][2]), "r"(af[mi][3]),
                          "r"(bf[nj][0]), "r"(bf[nj][1]));
                }
        }
        __syncthreads();
    }

#pragma unroll
    for (int mi = 0; mi < 4; mi++) {
        int row0 = rowbase + mwarp + mi * 16 + g;
        int row1 = row0 + 8;
#pragma unroll
        for (int nj = 0; nj < 4; nj++) {
            int n = nwarp + nj * 8 + 2 * t4;
            if (wc < 2) {
                if (row0 < nrows)
                    *(float2*)(Cs + (size_t)row0 * DOUT + n) =
                        make_float2(c[mi][nj][0], c[mi][nj][1]);
                if (row1 < nrows)
                    *(float2*)(Cs + (size_t)row1 * DOUT + n) =
                        make_float2(c[mi][nj][2], c[mi][nj][3]);
            } else {
                int nn = n - 64;
                if (row0 < nrows)
                    *(__half2*)(Cr + (size_t)row0 * DOUT + nn) =
                        __floats2half2_rn(c[mi][nj][0], c[mi][nj][1]);
                if (row1 < nrows)
                    *(__half2*)(Cr + (size_t)row1 * DOUT + nn) =
                        __floats2half2_rn(c[mi][nj][2], c[mi][nj][3]);
            }
        }
    }
}

// ---------------- launch ----------------
extern "C" void kernel_launch(void* const* d_in, const int* in_sizes, int n_in,
                              void* d_out, int out_size) {
    const float* x_p       = (const float*)d_in[0];
    const float* x_a       = (const float*)d_in[1];
    const int*   adj_a_row = (const int*)d_in[2];
    const int*   adj_a_col = (const int*)d_in[3];
    const float* adj_a_val = (const float*)d_in[4];
    const int*   adj_p_row = (const int*)d_in[5];
    const int*   adj_p_col = (const int*)d_in[6];
    const float* adj_p_val = (const float*)d_in[7];
    const float* w_self_p  = (const float*)d_in[8];
    const float* w_rel_p_a = (const float*)d_in[9];
    const float* bias_p    = (const float*)d_in[10];
    const float* w_query_p = (const float*)d_in[11];
    const float* w_keys_p  = (const float*)d_in[12];
    const float* w_att_p   = (const float*)d_in[13];
    const float* w_self_a  = (const float*)d_in[14];
    const float* w_rel_a_p = (const float*)d_in[15];
    const float* bias_a    = (const float*)d_in[16];
    const float* w_query_a = (const float*)d_in[17];
    const float* w_keys_a  = (const float*)d_in[18];
    const float* w_att_a   = (const float*)d_in[19];

    float* out = (float*)d_out;
    float* out_p = out;
    float* out_a = out + (size_t)NNODES * DOUT;
    float* att_p = out + (size_t)2 * NNODES * DOUT;
    float* att_a = att_p + (size_t)NNODES * 2;

    float *p_self_p, *p_self_a, *p_vkq;
    __half2 *p_rels_p, *p_rels_a;
    int *p_cnt, *p_off, *p_cur, *p_bsum;
    int2 *p_edge;
    cudaGetSymbolAddress((void**)&p_self_p, g_self_p);
    cudaGetSymbolAddress((void**)&p_self_a, g_self_a);
    cudaGetSymbolAddress((void**)&p_rels_p, g_rels_p);
    cudaGetSymbolAddress((void**)&p_rels_a, g_rels_a);
    cudaGetSymbolAddress((void**)&p_vkq, g_vkq);
    cudaGetSymbolAddress((void**)&p_cnt, g_cnt);
    cudaGetSymbolAddress((void**)&p_off, g_off);
    cudaGetSymbolAddress((void**)&p_cur, g_cur);
    cudaGetSymbolAddress((void**)&p_bsum, g_bsum);
    cudaGetSymbolAddress((void**)&p_edge, g_edge);

    static cudaStream_t s1 = nullptr, s2 = nullptr, s3 = nullptr;
    static cudaEvent_t e_fork = nullptr, e_b0 = nullptr,
                       e_ga = nullptr, e_gp = nullptr, e_s2 = nullptr, e_s3 = nullptr;
    if (s1 == nullptr) {
        cudaStreamCreateWithFlags(&s1, cudaStreamNonBlocking);
        cudaStreamCreateWithFlags(&s2, cudaStreamNonBlocking);
        cudaStreamCreateWithFlags(&s3, cudaStreamNonBlocking);
        cudaEventCreateWithFlags(&e_fork, cudaEventDisableTiming);
        cudaEventCreateWithFlags(&e_b0, cudaEventDisableTiming);
        cudaEventCreateWithFlags(&e_ga, cudaEventDisableTiming);
        cudaEventCreateWithFlags(&e_gp, cudaEventDisableTiming);
        cudaEventCreateWithFlags(&e_s2, cudaEventDisableTiming);
        cudaEventCreateWithFlags(&e_s3, cudaEventDisableTiming);
        cudaFuncSetAttribute(gemm_tf32_kernel,
                             cudaFuncAttributeMaxDynamicSharedMemorySize, GEMM_SMEM_BYTES);
    }

    const int EB = (NEDGE + 255) / 256;
    const int NBK = (NNODES + 255) / 256;
    const int gblocks = (NNODES + GBM - 1) / GBM;
    const int wblocks = (NNODES * 32 + 127) / 128;   // 128-thread SpMM blocks

    // fork: s1 builds rel0, s2 builds rel1 (concurrent), s0 runs GEMMs
    cudaEventRecord(e_fork, 0);
    cudaStreamWaitEvent(s1, e_fork, 0);
    cudaStreamWaitEvent(s2, e_fork, 0);

    // ---- s1: CSR build rel0 (adj_a) ----
    vkq_kernel<<<1, 256, 0, s1>>>(w_keys_p, w_query_p, w_att_p, w_keys_a, w_query_a, w_att_a);
    zero_cnt_kernel<<<NBK, 256, 0, s1>>>(p_cnt);
    hist_kernel<<<EB, 256, 0, s1>>>(adj_a_row, p_cnt);
    scan1_kernel<<<NB, SCAN_BLK, 0, s1>>>(p_cnt, p_off, p_bsum);
    scan2_kernel<<<1, 128, 0, s1>>>(p_bsum);
    scan3_kernel<<<NBK, 256, 0, s1>>>(p_off, p_cur, p_bsum);
    scatter_kernel<<<EB, 256, 0, s1>>>(adj_a_row, adj_a_col, adj_a_val, p_cur, p_edge);
    cudaEventRecord(e_b0, s1);

    // ---- s2: CSR build rel1 (adj_p) — concurrent with s1; spmm1 follows in-stream ----
    zero_cnt_kernel<<<NBK, 256, 0, s2>>>(p_cnt + NNODES);
    hist_kernel<<<EB, 256, 0, s2>>>(adj_p_row, p_cnt + NNODES);
    scan1_kernel<<<NB, SCAN_BLK, 0, s2>>>(p_cnt + NNODES, p_off + NNODES, p_bsum + (NB + 1));
    scan2_kernel<<<1, 128, 0, s2>>>(p_bsum + (NB + 1));
    scan3_kernel<<<NBK, 256, 0, s2>>>(p_off + NNODES, p_cur + NNODES, p_bsum + (NB + 1));
    scatter_kernel<<<EB, 256, 0, s2>>>(adj_p_row, adj_p_col, adj_p_val, p_cur + NNODES,
                                       p_edge + NEDGE);

    // ---- s0: pipelined tf32 GEMMs ----
    gemm_tf32_kernel<<<gblocks, 256, GEMM_SMEM_BYTES>>>(x_a, w_self_a, w_rel_p_a,
                                                        p_self_a, (__half*)p_rels_a, NNODES);
    cudaEventRecord(e_ga, 0);
    gemm_tf32_kernel<<<gblocks, 256, GEMM_SMEM_BYTES>>>(x_p, w_self_p, w_rel_a_p,
                                                        p_self_p, (__half*)p_rels_p, NNODES);
    cudaEventRecord(e_gp, 0);

    // ---- s3: spmm+finalize rel0 (out_p) — needs build0 + gemm_a ----
    cudaStreamWaitEvent(s3, e_b0, 0);
    cudaStreamWaitEvent(s3, e_ga, 0);
    spmm_final_kernel<<<wblocks, 128, 0, s3>>>(p_off, p_cnt, p_edge, p_rels_a, p_self_p, bias_p,
                                               p_vkq + 0 * DOUT, p_vkq + 1 * DOUT, out_p, att_p);
    cudaEventRecord(e_s3, s3);

    // ---- s2: spmm+finalize rel1 (out_a) — in-stream after build1; waits gemm_p ----
    cudaStreamWaitEvent(s2, e_gp, 0);
    spmm_final_kernel<<<wblocks, 128, 0, s2>>>(p_off + NNODES, p_cnt + NNODES, p_edge + NEDGE,
                                               p_rels_p, p_self_a, bias_a,
                                               p_vkq + 2 * DOUT, p_vkq + 3 * DOUT, out_a, att_a);
    cudaEventRecord(e_s2, s2);

    // join both SpMM streams back into the origin stream
    cudaStreamWaitEvent(0, e_s3, 0);
    cudaStreamWaitEvent(0, e_s2, 0);
}